// round 16
// baseline (speedup 1.0000x reference)
#include <cuda_runtime.h>
#include <cuda_fp16.h>
#include <math.h>
#include <stdint.h>

// Shapes
#define Bz 2
#define Tt 768
#define tt 256
#define Cc 768
#define Hh 12
#define FC 3072
#define Vv 512

// Weight offsets (halfs) inside g_wh
#define OFF_QKV0 0
#define OFF_QKV1 10616832
#define OFF_PROJ0 21233664
#define OFF_PROJ1 24772608
#define OFF_FC10 28311552
#define OFF_FC11 42467328
#define OFF_FC20 56623104
#define OFF_FC21 70778880
#define OFF_HUP 84934656
#define OFF_HDN 85327872
#define WH_TOTAL 85721088

// Scratch (allocation-free: __device__ globals)
__device__ float g_x[Bz * Tt * Cc];
__device__ __half g_hh[Bz * Tt * Cc];
__device__ __half g_yh[Bz * Tt * Cc];
__device__ __half g_bigh[Bz * Tt * FC];
__device__ __half g_wh[WH_TOTAL];

// ---------------------------------------------------------------------------
// helpers
// ---------------------------------------------------------------------------
__device__ __forceinline__ unsigned packh2(float lo, float hi) {
  unsigned u;
  asm("cvt.rn.f16x2.f32 %0, %1, %2;" : "=r"(u) : "f"(hi), "f"(lo));
  return u;
}
__device__ __forceinline__ uint32_t smem_u32(const void* p) {
  uint32_t a;
  asm("{ .reg .u64 t; cvta.to.shared.u64 t, %1; cvt.u32.u64 %0, t; }" : "=r"(a) : "l"(p));
  return a;
}
__device__ __forceinline__ void cp16(uint32_t s, const void* g) {
  asm volatile("cp.async.cg.shared.global [%0], [%1], 16;" :: "r"(s), "l"(g));
}

__device__ __forceinline__ void mma16h(float* c, const unsigned* a, const unsigned* b) {
  asm volatile(
      "mma.sync.aligned.m16n8k16.row.col.f32.f16.f16.f32 "
      "{%0,%1,%2,%3},{%4,%5,%6,%7},{%8,%9},{%0,%1,%2,%3};"
      : "+f"(c[0]), "+f"(c[1]), "+f"(c[2]), "+f"(c[3])
      : "r"(a[0]), "r"(a[1]), "r"(a[2]), "r"(a[3]), "r"(b[0]), "r"(b[1]));
}

// ---------------------------------------------------------------------------
// single fused fp32 -> fp16 weight conversion (all 10 tensors, one launch)
// ---------------------------------------------------------------------------
__global__ __launch_bounds__(256) void cvt_all(
    const float* s0, const float* s1, const float* s2, const float* s3,
    const float* s4, const float* s5, const float* s6, const float* s7,
    const float* s8, const float* s9, __half* __restrict__ wh) {
  int blk = blockIdx.x;
  const float* src;
  size_t off;
  int base;
  if (blk < 10368)      { src = s0; off = OFF_QKV0;  base = 0; }
  else if (blk < 20736) { src = s1; off = OFF_QKV1;  base = 10368; }
  else if (blk < 24192) { src = s2; off = OFF_PROJ0; base = 20736; }
  else if (blk < 27648) { src = s3; off = OFF_PROJ1; base = 24192; }
  else if (blk < 41472) { src = s4; off = OFF_FC10;  base = 27648; }
  else if (blk < 55296) { src = s5; off = OFF_FC11;  base = 41472; }
  else if (blk < 69120) { src = s6; off = OFF_FC20;  base = 55296; }
  else if (blk < 82944) { src = s7; off = OFF_FC21;  base = 69120; }
  else if (blk < 83328) { src = s8; off = OFF_HUP;   base = 82944; }
  else                  { src = s9; off = OFF_HDN;   base = 83328; }
  int i = (blk - base) * 256 + threadIdx.x;
  float4 v = ((const float4*)src)[i];
  uint2 u = {packh2(v.x, v.y), packh2(v.z, v.w)};
  ((uint2*)(wh + off))[i] = u;
}

// ---------------------------------------------------------------------------
// fp16 tensor-core GEMM (fp32 accum), 4-stage cp.async pipeline (wait 2).
// 256 threads (8 warps: 2M x 4N), warp tile (BM/2) x (BN/4).
// Block BM x BN, Ktile 32. Smem per stage: A BM x 80B, B BN x 80B.
// zIn/zOut: element strides applied per blockIdx.z (0 for non-batched).
// MODE 0: f32 write; 1: GELU->half; 2: residual add f32; 3: ->half.
// ---------------------------------------------------------------------------
template <int BM, int BN, int MODE>
__global__ __launch_bounds__(256, 2) void gemm_h(
    const __half* __restrict__ In, int ldIn,
    const __half* __restrict__ W,      // [N][K] halfs
    const float* __restrict__ bias,    // [N] or nullptr
    void* __restrict__ Outv, int ldOut, int K,
    int zIn, int zOut) {
  extern __shared__ char smc[];
  unsigned* smu = (unsigned*)smc;
  const uint32_t sbase = smem_u32(smc);
  constexpr int A_STAGE = BM * 80;
  constexpr int B_OFF = 4 * A_STAGE;
  constexpr int B_STAGE = BN * 80;
  constexpr int ACH = (BM * 4) / 256;
  constexpr int BCH = (BN * 4) / 256;
  constexpr int MB = BM / 32;     // m frags per warp (warp tile BM/2)
  constexpr int NB = BN / 32;     // n frags per warp (warp tile BN/4)

  In += (size_t)blockIdx.z * zIn;

  const int tid = threadIdx.x;
  const int lane = tid & 31, warp = tid >> 5;
  const int wm = warp & 1, wn = warp >> 1;
  const int g = lane >> 2, q = lane & 3;
  const int m0 = blockIdx.y * BM, n0 = blockIdx.x * BN;

  float acc[MB][NB][4];
#pragma unroll
  for (int mb = 0; mb < MB; mb++)
#pragma unroll
    for (int nb = 0; nb < NB; nb++)
#pragma unroll
      for (int r = 0; r < 4; r++) acc[mb][nb][r] = 0.f;

  const int NT = K / 32;

  auto load_tile = [&](int t, int s) {
#pragma unroll
    for (int j = 0; j < ACH; j++) {
      int c = tid + j * 256;
      int row = c >> 2, sub = c & 3;
      cp16(sbase + s * A_STAGE + row * 80 + sub * 16,
           In + (size_t)(m0 + row) * ldIn + t * 32 + sub * 8);
    }
#pragma unroll
    for (int j = 0; j < BCH; j++) {
      int c = tid + j * 256;
      int row = c >> 2, sub = c & 3;
      cp16(sbase + B_OFF + s * B_STAGE + row * 80 + sub * 16,
           W + (size_t)(n0 + row) * K + t * 32 + sub * 8);
    }
  };

  load_tile(0, 0);
  asm volatile("cp.async.commit_group;" ::: "memory");
  if (NT > 1) load_tile(1, 1);
  asm volatile("cp.async.commit_group;" ::: "memory");
  if (NT > 2) load_tile(2, 2);
  asm volatile("cp.async.commit_group;" ::: "memory");

  int st = 0;
  for (int t = 0; t < NT; t++) {
    asm volatile("cp.async.wait_group 2;" ::: "memory");
    __syncthreads();

    const unsigned* Ab = smu + st * (A_STAGE / 4);
    const unsigned* Bb = smu + (B_OFF + st * B_STAGE) / 4;
#pragma unroll
    for (int ks = 0; ks < 2; ks++) {
      const int k0 = ks * 8;
      unsigned a[MB][4], b[NB][2];
#pragma unroll
      for (int mb = 0; mb < MB; mb++) {
        int r = wm * (BM / 2) + mb * 16 + g;
        a[mb][0] = Ab[r * 20 + k0 + q];
        a[mb][1] = Ab[(r + 8) * 20 + k0 + q];
        a[mb][2] = Ab[r * 20 + k0 + q + 4];
        a[mb][3] = Ab[(r + 8) * 20 + k0 + q + 4];
      }
#pragma unroll
      for (int nb = 0; nb < NB; nb++) {
        int c = wn * (BN / 4) + nb * 8 + g;
        b[nb][0] = Bb[c * 20 + k0 + q];
        b[nb][1] = Bb[c * 20 + k0 + q + 4];
      }
#pragma unroll
      for (int mb = 0; mb < MB; mb++)
#pragma unroll
        for (int nb = 0; nb < NB; nb++) mma16h(acc[mb][nb], a[mb], b[nb]);
    }

    if (t + 3 < NT) load_tile(t + 3, (st + 3) & 3);
    asm volatile("cp.async.commit_group;" ::: "memory");
    st = (st + 1) & 3;
  }

  float* Outf = (float*)Outv + (size_t)blockIdx.z * zOut;
  __half* Outh = (__half*)Outv + (size_t)blockIdx.z * zOut;
#pragma unroll
  for (int mb = 0; mb < MB; mb++) {
#pragma unroll
    for (int nb = 0; nb < NB; nb++) {
      int row = m0 + wm * (BM / 2) + mb * 16 + g;
      int col = n0 + wn * (BN / 4) + nb * 8 + 2 * q;
      float b0v = bias ? bias[col] : 0.f;
      float b1v = bias ? bias[col + 1] : 0.f;
      float v00 = acc[mb][nb][0] + b0v, v01 = acc[mb][nb][1] + b1v;
      float v10 = acc[mb][nb][2] + b0v, v11 = acc[mb][nb][3] + b1v;
      if (MODE == 1) {
        v00 = 0.5f * v00 * (1.f + erff(v00 * 0.7071067811865476f));
        v01 = 0.5f * v01 * (1.f + erff(v01 * 0.7071067811865476f));
        v10 = 0.5f * v10 * (1.f + erff(v10 * 0.7071067811865476f));
        v11 = 0.5f * v11 * (1.f + erff(v11 * 0.7071067811865476f));
      }
      if (MODE == 0 || MODE == 2) {
        float* p0 = Outf + (size_t)row * ldOut + col;
        float* p1 = Outf + (size_t)(row + 8) * ldOut + col;
        if (MODE == 2) {
          float2 o0 = *(const float2*)p0;
          float2 o1 = *(const float2*)p1;
          v00 += o0.x; v01 += o0.y; v10 += o1.x; v11 += o1.y;
        }
        *(float2*)p0 = make_float2(v00, v01);
        *(float2*)p1 = make_float2(v10, v11);
      } else {
        *(unsigned*)(Outh + (size_t)row * ldOut + col) = packh2(v00, v01);
        *(unsigned*)(Outh + (size_t)(row + 8) * ldOut + col) = packh2(v10, v11);
      }
    }
  }
}

// ---------------------------------------------------------------------------
// fp32 fallback GEMM (cond embed, K=438), batched over blockIdx.z (batch),
// with pos-emb add fused into the epilogue.
// ---------------------------------------------------------------------------
__global__ __launch_bounds__(256) void gemm_f32(
    const float* __restrict__ In, int ldIn, const float* __restrict__ W,
    const float* __restrict__ bias, const float* __restrict__ pos,
    float* __restrict__ Out, int ldOut, int K) {
  __shared__ float As[16][132];
  __shared__ float Bs[16][68];
  const int tid = threadIdx.x;
  const int tx = tid & 15, ty = tid >> 4;
  const int m0 = blockIdx.y * 128, n0 = blockIdx.x * 64;
  const int bz = blockIdx.z;
  const float* Inb = In + (size_t)bz * tt * ldIn;
  float* Outb = Out + (size_t)bz * Tt * ldOut;
  const int lr = tid >> 2, lc = (tid & 3) * 4;
  float acc[8][4];
#pragma unroll
  for (int r = 0; r < 8; r++)
#pragma unroll
    for (int c = 0; c < 4; c++) acc[r][c] = 0.f;
  for (int kt = 0; kt < K; kt += 16) {
#pragma unroll
    for (int qq = 0; qq < 4; qq++) {
      int k = kt + lc + qq;
      float av0 = 0.f, av1 = 0.f, bv = 0.f;
      if (k < K) {
        av0 = Inb[(size_t)(m0 + lr) * ldIn + k];
        av1 = Inb[(size_t)(m0 + lr + 64) * ldIn + k];
        bv = W[(size_t)(n0 + lr) * K + k];
      }
      As[lc + qq][lr] = av0;
      As[lc + qq][lr + 64] = av1;
      Bs[lc + qq][lr] = bv;
    }
    __syncthreads();
#pragma unroll
    for (int kk = 0; kk < 16; kk++) {
      float4 t0 = *(const float4*)&As[kk][ty * 8];
      float4 t1 = *(const float4*)&As[kk][ty * 8 + 4];
      float4 t2 = *(const float4*)&Bs[kk][tx * 4];
      float a[8] = {t0.x, t0.y, t0.z, t0.w, t1.x, t1.y, t1.z, t1.w};
      float bb[4] = {t2.x, t2.y, t2.z, t2.w};
#pragma unroll
      for (int r = 0; r < 8; r++)
#pragma unroll
        for (int c = 0; c < 4; c++) acc[r][c] += a[r] * bb[c];
    }
    __syncthreads();
  }
  float bv[4];
#pragma unroll
  for (int c = 0; c < 4; c++) bv[c] = bias ? bias[n0 + tx * 4 + c] : 0.f;
#pragma unroll
  for (int r = 0; r < 8; r++) {
    int row = m0 + ty * 8 + r;
    const float* pr = pos + (size_t)row * Cc + n0 + tx * 4;
    float* op = Outb + (size_t)row * ldOut + n0 + tx * 4;
    float4 o = {acc[r][0] + bv[0] + pr[0], acc[r][1] + bv[1] + pr[1],
                acc[r][2] + bv[2] + pr[2], acc[r][3] + bv[3] + pr[3]};
    *(float4*)op = o;
  }
}

// ---------------------------------------------------------------------------
// LayerNorm (proven): block-per-row, fp32 in, fp16 out
// ---------------------------------------------------------------------------
__global__ __launch_bounds__(256) void ln_kernel(
    const float* __restrict__ x, const float* __restrict__ w,
    const float* __restrict__ b, __half* __restrict__ out) {
  const int row = blockIdx.x;
  const int tid = threadIdx.x;
  const float* xr = x + (size_t)row * Cc;
  float v0 = xr[tid], v1 = xr[tid + 256], v2 = xr[tid + 512];
  __shared__ float red[8];
  float s = v0 + v1 + v2;
#pragma unroll
  for (int o = 16; o > 0; o >>= 1) s += __shfl_xor_sync(0xffffffffu, s, o);
  if ((tid & 31) == 0) red[tid >> 5] = s;
  __syncthreads();
  float mean = (red[0] + red[1] + red[2] + red[3] + red[4] + red[5] + red[6] + red[7]) * (1.f / 768.f);
  float d0 = v0 - mean, d1 = v1 - mean, d2 = v2 - mean;
  float sq = d0 * d0 + d1 * d1 + d2 * d2;
  __syncthreads();
#pragma unroll
  for (int o = 16; o > 0; o >>= 1) sq += __shfl_xor_sync(0xffffffffu, sq, o);
  if ((tid & 31) == 0) red[tid >> 5] = sq;
  __syncthreads();
  float var = (red[0] + red[1] + red[2] + red[3] + red[4] + red[5] + red[6] + red[7]) * (1.f / 768.f);
  float inv = rsqrtf(var + 1e-5f);
  __half* orow = out + (size_t)row * Cc;
  orow[tid] = __float2half_rn(d0 * inv * w[tid] + b[tid]);
  orow[tid + 256] = __float2half_rn(d1 * inv * w[tid + 256] + b[tid + 256]);
  orow[tid + 512] = __float2half_rn(d2 * inv * w[tid + 512] + b[tid + 512]);
}

// ---------------------------------------------------------------------------
// Embed token rows only (rows tt..3tt per batch): x = tok[idx] + pos
// ---------------------------------------------------------------------------
__global__ __launch_bounds__(256) void embed_tok(
    const int* __restrict__ iu, const int* __restrict__ idn,
    const float* __restrict__ tu, const float* __restrict__ td,
    const float* __restrict__ pos, float* __restrict__ x) {
  int gidx = blockIdx.x * 256 + threadIdx.x;
  int c = gidx % Cc;
  int r2 = gidx / Cc;
  int i2 = r2 % (2 * tt);
  int b = r2 / (2 * tt);
  int i = tt + i2;
  float p = pos[i * Cc + c];
  float v;
  if (i2 < tt) v = tu[(size_t)iu[b * tt + i2] * Cc + c] + p;
  else v = td[(size_t)idn[b * tt + (i2 - tt)] * Cc + c] + p;
  x[((size_t)b * Tt + i) * Cc + c] = v;
}

// ---------------------------------------------------------------------------
// fp16 flash attention (unchanged)
// ---------------------------------------------------------------------------
__global__ __launch_bounds__(128) void attn_h(
    const __half* __restrict__ qkv, __half* __restrict__ y) {
  __shared__ __align__(16) unsigned Qs[64][36];
  __shared__ __align__(16) unsigned Ks[64][36];
  __shared__ __align__(16) unsigned Vt[64][36];
  __shared__ __align__(16) unsigned Ps[64][36];
  __half(*VtH)[72] = (__half(*)[72])Vt;

  const int qt = blockIdx.x, h = blockIdx.y, b = blockIdx.z;
  const int tid = threadIdx.x, lane = tid & 31, warp = tid >> 5;
  const int g = lane >> 2, q = lane & 3;

  const int lrow = tid >> 1;
  const int lwo = (tid & 1) * 16;
  const int ldh = lwo * 2;

  {
    const __half* qr = qkv + (size_t)(b * Tt + qt * 64 + lrow) * 2304 + h * 64 + ldh;
#pragma unroll
    for (int j = 0; j < 4; j++)
      *(uint4*)&Qs[lrow][lwo + j * 4] = *(const uint4*)(qr + j * 8);
  }

  float m0r = -1e30f, m1r = -1e30f, l0 = 0.f, l1 = 0.f;
  float accO[8][4];
#pragma unroll
  for (int nb = 0; nb < 8; nb++)
#pragma unroll
    for (int r = 0; r < 4; r++) accO[nb][r] = 0.f;

  const int a = qt & 3;
  const int r0 = warp * 16 + g, r1 = r0 + 8;

  for (int kt = 0; kt < 12; kt++) {
    if ((kt & 3) > a) continue;
    const bool diag = ((kt & 3) == a);
    __syncthreads();
    {
      const __half* kr = qkv + (size_t)(b * Tt + kt * 64 + lrow) * 2304 + 768 + h * 64 + ldh;
#pragma unroll
      for (int j = 0; j < 4; j++)
        *(uint4*)&Ks[lrow][lwo + j * 4] = *(const uint4*)(kr + j * 8);
      const __half* vr = kr + 768;
#pragma unroll
      for (int d2 = 0; d2 < 32; d2 += 2) {
        __half2 v = *(const __half2*)(vr + d2);
        VtH[ldh + d2][lrow] = __low2half(v);
        VtH[ldh + d2 + 1][lrow] = __high2half(v);
      }
    }
    __syncthreads();

    float s[8][4];
#pragma unroll
    for (int nb = 0; nb < 8; nb++)
#pragma unroll
      for (int r = 0; r < 4; r++) s[nb][r] = 0.f;
#pragma unroll
    for (int ks = 0; ks < 4; ks++) {
      const int k0 = ks * 8;
      unsigned aa[4] = {Qs[r0][k0 + q], Qs[r1][k0 + q],
                        Qs[r0][k0 + q + 4], Qs[r1][k0 + q + 4]};
#pragma unroll
      for (int nb = 0; nb < 8; nb++) {
        const int c = nb * 8 + g;
        unsigned bb[2] = {Ks[c][k0 + q], Ks[c][k0 + q + 4]};
        mma16h(s[nb], aa, bb);
      }
    }

    float mx0 = -1e30f, mx1 = -1e30f;
#pragma unroll
    for (int nb = 0; nb < 8; nb++) {
      int c0 = nb * 8 + 2 * q;
      float v00 = s[nb][0] * 0.125f, v01 = s[nb][1] * 0.125f;
      float v10 = s[nb][2] * 0.125f, v11 = s[nb][3] * 0.125f;
      if (diag) {
        if (c0 > r0) v00 = -1e30f;
        if (c0 + 1 > r0) v01 = -1e30f;
        if (c0 > r1) v10 = -1e30f;
        if (c0 + 1 > r1) v11 = -1e30f;
      }
      s[nb][0] = v00; s[nb][1] = v01; s[nb][2] = v10; s[nb][3] = v11;
      mx0 = fmaxf(mx0, fmaxf(v00, v01));
      mx1 = fmaxf(mx1, fmaxf(v10, v11));
    }
    mx0 = fmaxf(mx0, __shfl_xor_sync(0xffffffffu, mx0, 1));
    mx0 = fmaxf(mx0, __shfl_xor_sync(0xffffffffu, mx0, 2));
    mx1 = fmaxf(mx1, __shfl_xor_sync(0xffffffffu, mx1, 1));
    mx1 = fmaxf(mx1, __shfl_xor_sync(0xffffffffu, mx1, 2));

    float mn0 = fmaxf(m0r, mx0), mn1 = fmaxf(m1r, mx1);
    float cf0 = __expf(m0r - mn0), cf1 = __expf(m1r - mn1);
    m0r = mn0; m1r = mn1;

    float rs0 = 0.f, rs1 = 0.f;
#pragma unroll
    for (int nb = 0; nb < 8; nb++) {
      float p00 = __expf(s[nb][0] - mn0);
      float p01 = __expf(s[nb][1] - mn0);
      float p10 = __expf(s[nb][2] - mn1);
      float p11 = __expf(s[nb][3] - mn1);
      rs0 += p00 + p01;
      rs1 += p10 + p11;
      Ps[r0][nb * 4 + q] = packh2(p00, p01);
      Ps[r1][nb * 4 + q] = packh2(p10, p11);
    }
    rs0 += __shfl_xor_sync(0xffffffffu, rs0, 1);
    rs0 += __shfl_xor_sync(0xffffffffu, rs0, 2);
    rs1 += __shfl_xor_sync(0xffffffffu, rs1, 1);
    rs1 += __shfl_xor_sync(0xffffffffu, rs1, 2);
    l0 = l0 * cf0 + rs0;
    l1 = l1 * cf1 + rs1;
#pragma unroll
    for (int nb = 0; nb < 8; nb++) {
      accO[nb][0] *= cf0; accO[nb][1] *= cf0;
      accO[nb][2] *= cf1; accO[nb][3] *= cf1;
    }
    __syncthreads();

#pragma unroll
    for (int ks = 0; ks < 4; ks++) {
      const int k0 = ks * 8;
      unsigned aa[4] = {Ps[r0][k0 + q], Ps[r1][k0 + q],
                        Ps[r0][k0 + q + 4], Ps[r1][k0 + q + 4]};
#pragma unroll
      for (int nb = 0; nb < 8; nb++) {
        const int c = nb * 8 + g;
        unsigned bb[2] = {Vt[c][k0 + q], Vt[c][k0 + q + 4]};
        mma16h(accO[nb], aa, bb);
      }
    }
  }

  float inv0 = 1.f / l0, inv1 = 1.f / l1;
#pragma unroll
  for (int nb = 0; nb < 8; nb++) {
    int c0 = nb * 8 + 2 * q;
    __half* y0 = y + (size_t)(b * Tt + qt * 64 + r0) * Cc + h * 64 + c0;
    *(unsigned*)y0 = packh2(accO[nb][0] * inv0, accO[nb][1] * inv0);
    *(unsigned*)(y0 + 8 * Cc) = packh2(accO[nb][2] * inv1, accO[nb][3] * inv1);
  }
}

// ---------------------------------------------------------------------------
// Launcher
// ---------------------------------------------------------------------------
extern "C" void kernel_launch(void* const* d_in, const int* in_sizes, int n_in,
                              void* d_out, int out_size) {
  const int* idx_up = nullptr; const int* idx_down = nullptr;
  const float *cond = 0, *tok_up = 0, *tok_down = 0, *pos = 0, *cond_w = 0, *cond_b = 0;
  const float *lnf_w = 0, *lnf_b = 0, *hup = 0, *hdn = 0;
  const float *ln1[2] = {0, 0}, *ln2[2] = {0, 0}, *qkvw[2] = {0, 0}, *qkvb[2] = {0, 0};
  const float *projw[2] = {0, 0}, *projb[2] = {0, 0};
  const float *fc1w[2] = {0, 0}, *fc1b[2] = {0, 0}, *fc2w[2] = {0, 0}, *fc2b[2] = {0, 0};

  int c512 = 0, c393 = 0, c768 = 0, c9216 = 0, cqw = 0, cqb = 0, cpw = 0, c4608 = 0,
      cfw = 0, cfb = 0;
  for (int i = 0; i < n_in; i++) {
    const float* f = (const float*)d_in[i];
    switch (in_sizes[i]) {
      case 512:       if (c512 == 0) idx_up = (const int*)f; else idx_down = (const int*)f; c512++; break;
      case 224256:    cond = f; break;
      case 393216:    if (c393 == 0) tok_up = f; else if (c393 == 1) tok_down = f;
                      else if (c393 == 2) hup = f; else hdn = f; c393++; break;
      case 589824:    pos = f; break;
      case 336384:    cond_w = f; break;
      case 768:       if (c768 == 0) cond_b = f; else if (c768 == 1) lnf_w = f; else lnf_b = f; c768++; break;
      case 9216:      if (c9216 == 0) ln1[0] = f; else if (c9216 == 1) ln2[0] = f;
                      else if (c9216 == 2) ln1[1] = f; else ln2[1] = f; c9216++; break;
      case 10616832:  qkvw[cqw++] = f; break;
      case 13824:     qkvb[cqb++] = f; break;
      case 3538944:   projw[cpw++] = f; break;
      case 4608:      if (c4608 == 0) projb[0] = f; else if (c4608 == 1) fc2b[0] = f;
                      else if (c4608 == 2) projb[1] = f; else fc2b[1] = f; c4608++; break;
      case 14155776:  if (cfw == 0) fc1w[0] = f; else if (cfw == 1) fc2w[0] = f;
                      else if (cfw == 2) fc1w[1] = f; else fc2w[1] = f; cfw++; break;
      case 18432:     fc1b[cfb++] = f; break;
      default: break;
    }
  }

  float* x;
  __half *hh, *yh, *bigh, *wh;
  cudaGetSymbolAddress((void**)&x, g_x);
  cudaGetSymbolAddress((void**)&hh, g_hh);
  cudaGetSymbolAddress((void**)&yh, g_yh);
  cudaGetSymbolAddress((void**)&bigh, g_bigh);
  cudaGetSymbolAddress((void**)&wh, g_wh);

  const size_t off_qkv[2] = {OFF_QKV0, OFF_QKV1};
  const size_t off_proj[2] = {OFF_PROJ0, OFF_PROJ1};
  const size_t off_fc1[2] = {OFF_FC10, OFF_FC11};
  const size_t off_fc2[2] = {OFF_FC20, OFF_FC21};

  // --- Weight conversion: one fused launch ---
  cvt_all<<<83712, 256>>>(qkvw[0], qkvw[1], projw[0], projw[1],
                          fc1w[0], fc1w[1], fc2w[0], fc2w[1], hup, hdn, wh);

  const int SM12864 = 4 * (128 * 80) + 4 * (64 * 80);  // 61440
  const int SM6464 = 4 * (64 * 80) + 4 * (64 * 80);    // 40960
  cudaFuncSetAttribute(gemm_h<128, 64, 3>, cudaFuncAttributeMaxDynamicSharedMemorySize, SM12864);
  cudaFuncSetAttribute(gemm_h<128, 64, 1>, cudaFuncAttributeMaxDynamicSharedMemorySize, SM12864);
  cudaFuncSetAttribute(gemm_h<64, 64, 2>, cudaFuncAttributeMaxDynamicSharedMemorySize, SM6464);
  cudaFuncSetAttribute(gemm_h<64, 64, 0>, cudaFuncAttributeMaxDynamicSharedMemorySize, SM6464);

  // --- Embed: one batched cond GEMM (pos fused) + token rows ---
  gemm_f32<<<dim3(Cc / 64, tt / 128, Bz), 256>>>(
      cond, 438, cond_w, cond_b, pos, x, Cc, 438);
  embed_tok<<<(Bz * 2 * tt * Cc) / 256, 256>>>(idx_up, idx_down, tok_up, tok_down, pos, x);

  // --- 2 stacks x 6 blocks ---
  for (int st = 0; st < 2; st++) {
    for (int l = 0; l < 6; l++) {
      const float* w1 = ln1[st] + (size_t)l * 2 * Cc;
      ln_kernel<<<Bz * Tt, 256>>>(x, w1, w1 + Cc, hh);
      gemm_h<128, 64, 3><<<dim3(3 * Cc / 64, Bz * Tt / 128), 256, SM12864>>>(
          hh, Cc, wh + off_qkv[st] + (size_t)l * 3 * Cc * Cc,
          qkvb[st] + (size_t)l * 3 * Cc, bigh, 3 * Cc, Cc, 0, 0);
      attn_h<<<dim3(Tt / 64, Hh, Bz), 128>>>(bigh, yh);
      gemm_h<64, 64, 2><<<dim3(Cc / 64, Bz * Tt / 64), 256, SM6464>>>(
          yh, Cc, wh + off_proj[st] + (size_t)l * Cc * Cc,
          projb[st] + (size_t)l * Cc, x, Cc, Cc, 0, 0);
      const float* w2 = ln2[st] + (size_t)l * 2 * Cc;
      ln_kernel<<<Bz * Tt, 256>>>(x, w2, w2 + Cc, hh);
      gemm_h<128, 64, 1><<<dim3(FC / 64, Bz * Tt / 128), 256, SM12864>>>(
          hh, Cc, wh + off_fc1[st] + (size_t)l * FC * Cc,
          fc1b[st] + (size_t)l * FC, bigh, FC, Cc, 0, 0);
      gemm_h<64, 64, 2><<<dim3(Cc / 64, Bz * Tt / 64), 256, SM6464>>>(
          bigh, FC, wh + off_fc2[st] + (size_t)l * Cc * FC,
          fc2b[st] + (size_t)l * Cc, x, Cc, FC, 0, 0);
    }
  }

  // --- Final LN + heads (batched over batch via grid.z) ---
  ln_kernel<<<Bz * Tt, 256>>>(x, lnf_w, lnf_b, hh);
  float* out = (float*)d_out;
  gemm_h<64, 64, 0><<<dim3(Vv / 64, tt / 64, Bz), 256, SM6464>>>(
      hh + (size_t)tt * Cc, Cc, wh + OFF_HUP, nullptr,
      out, Vv, Cc, Tt * Cc, tt * Vv);
  gemm_h<64, 64, 0><<<dim3(Vv / 64, tt / 64, Bz), 256, SM6464>>>(
      hh + (size_t)(2 * tt) * Cc, Cc, wh + OFF_HDN, nullptr,
      out + (size_t)Bz * tt * Vv, Vv, Cc, Tt * Cc, tt * Vv);
  (void)out_size; (void)n_in;
}

// round 17
// speedup vs baseline: 1.0960x; 1.0960x over previous
#include <cuda_runtime.h>
#include <cuda_fp16.h>
#include <math.h>
#include <stdint.h>

// Shapes
#define Bz 2
#define Tt 768
#define tt 256
#define Cc 768
#define Hh 12
#define FC 3072
#define Vv 512

// Weight offsets (halfs) inside g_wh
#define OFF_QKV0 0
#define OFF_QKV1 10616832
#define OFF_PROJ0 21233664
#define OFF_PROJ1 24772608
#define OFF_FC10 28311552
#define OFF_FC11 42467328
#define OFF_FC20 56623104
#define OFF_FC21 70778880
#define OFF_HUP 84934656
#define OFF_HDN 85327872
#define WH_TOTAL 85721088

// Scratch (allocation-free: __device__ globals)
__device__ float g_x[Bz * Tt * Cc];
__device__ __half g_hh[Bz * Tt * Cc];
__device__ __half g_yh[Bz * Tt * Cc];
__device__ __half g_bigh[Bz * Tt * FC];
__device__ __half g_wh[WH_TOTAL];

// ---------------------------------------------------------------------------
// helpers
// ---------------------------------------------------------------------------
__device__ __forceinline__ unsigned packh2(float lo, float hi) {
  unsigned u;
  asm("cvt.rn.f16x2.f32 %0, %1, %2;" : "=r"(u) : "f"(hi), "f"(lo));
  return u;
}
__device__ __forceinline__ uint32_t smem_u32(const void* p) {
  uint32_t a;
  asm("{ .reg .u64 t; cvta.to.shared.u64 t, %1; cvt.u32.u64 %0, t; }" : "=r"(a) : "l"(p));
  return a;
}
__device__ __forceinline__ void cp16(uint32_t s, const void* g) {
  asm volatile("cp.async.cg.shared.global [%0], [%1], 16;" :: "r"(s), "l"(g));
}

__device__ __forceinline__ void mma16h(float* c, const unsigned* a, const unsigned* b) {
  asm volatile(
      "mma.sync.aligned.m16n8k16.row.col.f32.f16.f16.f32 "
      "{%0,%1,%2,%3},{%4,%5,%6,%7},{%8,%9},{%0,%1,%2,%3};"
      : "+f"(c[0]), "+f"(c[1]), "+f"(c[2]), "+f"(c[3])
      : "r"(a[0]), "r"(a[1]), "r"(a[2]), "r"(a[3]), "r"(b[0]), "r"(b[1]));
}

// ---------------------------------------------------------------------------
// single fused fp32 -> fp16 weight conversion (all 10 tensors, one launch)
// ---------------------------------------------------------------------------
__global__ __launch_bounds__(256) void cvt_all(
    const float* s0, const float* s1, const float* s2, const float* s3,
    const float* s4, const float* s5, const float* s6, const float* s7,
    const float* s8, const float* s9, __half* __restrict__ wh) {
  int blk = blockIdx.x;
  const float* src;
  size_t off;
  int base;
  if (blk < 10368)      { src = s0; off = OFF_QKV0;  base = 0; }
  else if (blk < 20736) { src = s1; off = OFF_QKV1;  base = 10368; }
  else if (blk < 24192) { src = s2; off = OFF_PROJ0; base = 20736; }
  else if (blk < 27648) { src = s3; off = OFF_PROJ1; base = 24192; }
  else if (blk < 41472) { src = s4; off = OFF_FC10;  base = 27648; }
  else if (blk < 55296) { src = s5; off = OFF_FC11;  base = 41472; }
  else if (blk < 69120) { src = s6; off = OFF_FC20;  base = 55296; }
  else if (blk < 82944) { src = s7; off = OFF_FC21;  base = 69120; }
  else if (blk < 83328) { src = s8; off = OFF_HUP;   base = 82944; }
  else                  { src = s9; off = OFF_HDN;   base = 83328; }
  int i = (blk - base) * 256 + threadIdx.x;
  float4 v = ((const float4*)src)[i];
  uint2 u = {packh2(v.x, v.y), packh2(v.z, v.w)};
  ((uint2*)(wh + off))[i] = u;
}

// ---------------------------------------------------------------------------
// fp16 tensor-core GEMM (fp32 accum), 4-stage cp.async pipeline (wait 2).
// 256 threads (8 warps: 2M x 4N), warp tile (BM/2) x 32. BN fixed at 128.
// (round-15 winner configuration, restored)
// MODE 0: f32 write; 1: GELU->half; 2: residual add f32; 3: ->half.
// ---------------------------------------------------------------------------
template <int BM, int MODE>
__global__ __launch_bounds__(256, 2) void gemm_h(
    const __half* __restrict__ In, int ldIn,
    const __half* __restrict__ W,      // [N][K] halfs
    const float* __restrict__ bias,    // [N] or nullptr
    void* __restrict__ Outv, int ldOut, int K,
    int zIn, int zOut) {
  extern __shared__ char smc[];
  unsigned* smu = (unsigned*)smc;
  const uint32_t sbase = smem_u32(smc);
  constexpr int A_STAGE = BM * 80;
  constexpr int B_OFF = 4 * A_STAGE;
  constexpr int B_STAGE = 128 * 80;
  constexpr int ACH = (BM * 4) / 256;

  In += (size_t)blockIdx.z * zIn;

  const int tid = threadIdx.x;
  const int lane = tid & 31, warp = tid >> 5;
  const int wm = warp & 1, wn = warp >> 1;
  const int g = lane >> 2, q = lane & 3;
  const int m0 = blockIdx.y * BM, n0 = blockIdx.x * 128;

  constexpr int MB = BM / 32;

  float acc[MB][4][4];
#pragma unroll
  for (int mb = 0; mb < MB; mb++)
#pragma unroll
    for (int nb = 0; nb < 4; nb++)
#pragma unroll
      for (int r = 0; r < 4; r++) acc[mb][nb][r] = 0.f;

  const int NT = K / 32;

  auto load_tile = [&](int t, int s) {
#pragma unroll
    for (int j = 0; j < ACH; j++) {
      int c = tid + j * 256;
      int row = c >> 2, sub = c & 3;
      cp16(sbase + s * A_STAGE + row * 80 + sub * 16,
           In + (size_t)(m0 + row) * ldIn + t * 32 + sub * 8);
    }
#pragma unroll
    for (int j = 0; j < 2; j++) {
      int c = tid + j * 256;
      int row = c >> 2, sub = c & 3;
      cp16(sbase + B_OFF + s * B_STAGE + row * 80 + sub * 16,
           W + (size_t)(n0 + row) * K + t * 32 + sub * 8);
    }
  };

  load_tile(0, 0);
  asm volatile("cp.async.commit_group;" ::: "memory");
  if (NT > 1) load_tile(1, 1);
  asm volatile("cp.async.commit_group;" ::: "memory");
  if (NT > 2) load_tile(2, 2);
  asm volatile("cp.async.commit_group;" ::: "memory");

  int st = 0;
  for (int t = 0; t < NT; t++) {
    asm volatile("cp.async.wait_group 2;" ::: "memory");
    __syncthreads();

    const unsigned* Ab = smu + st * (A_STAGE / 4);
    const unsigned* Bb = smu + (B_OFF + st * B_STAGE) / 4;
#pragma unroll
    for (int ks = 0; ks < 2; ks++) {
      const int k0 = ks * 8;
      unsigned a[MB][4], b[4][2];
#pragma unroll
      for (int mb = 0; mb < MB; mb++) {
        int r = wm * (BM / 2) + mb * 16 + g;
        a[mb][0] = Ab[r * 20 + k0 + q];
        a[mb][1] = Ab[(r + 8) * 20 + k0 + q];
        a[mb][2] = Ab[r * 20 + k0 + q + 4];
        a[mb][3] = Ab[(r + 8) * 20 + k0 + q + 4];
      }
#pragma unroll
      for (int nb = 0; nb < 4; nb++) {
        int c = wn * 32 + nb * 8 + g;
        b[nb][0] = Bb[c * 20 + k0 + q];
        b[nb][1] = Bb[c * 20 + k0 + q + 4];
      }
#pragma unroll
      for (int mb = 0; mb < MB; mb++)
#pragma unroll
        for (int nb = 0; nb < 4; nb++) mma16h(acc[mb][nb], a[mb], b[nb]);
    }

    if (t + 3 < NT) load_tile(t + 3, (st + 3) & 3);
    asm volatile("cp.async.commit_group;" ::: "memory");
    st = (st + 1) & 3;
  }

  float* Outf = (float*)Outv + (size_t)blockIdx.z * zOut;
  __half* Outh = (__half*)Outv + (size_t)blockIdx.z * zOut;
#pragma unroll
  for (int mb = 0; mb < MB; mb++) {
#pragma unroll
    for (int nb = 0; nb < 4; nb++) {
      int row = m0 + wm * (BM / 2) + mb * 16 + g;
      int col = n0 + wn * 32 + nb * 8 + 2 * q;
      float b0v = bias ? bias[col] : 0.f;
      float b1v = bias ? bias[col + 1] : 0.f;
      float v00 = acc[mb][nb][0] + b0v, v01 = acc[mb][nb][1] + b1v;
      float v10 = acc[mb][nb][2] + b0v, v11 = acc[mb][nb][3] + b1v;
      if (MODE == 1) {
        v00 = 0.5f * v00 * (1.f + erff(v00 * 0.7071067811865476f));
        v01 = 0.5f * v01 * (1.f + erff(v01 * 0.7071067811865476f));
        v10 = 0.5f * v10 * (1.f + erff(v10 * 0.7071067811865476f));
        v11 = 0.5f * v11 * (1.f + erff(v11 * 0.7071067811865476f));
      }
      if (MODE == 0 || MODE == 2) {
        float* p0 = Outf + (size_t)row * ldOut + col;
        float* p1 = Outf + (size_t)(row + 8) * ldOut + col;
        if (MODE == 2) {
          float2 o0 = *(const float2*)p0;
          float2 o1 = *(const float2*)p1;
          v00 += o0.x; v01 += o0.y; v10 += o1.x; v11 += o1.y;
        }
        *(float2*)p0 = make_float2(v00, v01);
        *(float2*)p1 = make_float2(v10, v11);
      } else {
        *(unsigned*)(Outh + (size_t)row * ldOut + col) = packh2(v00, v01);
        *(unsigned*)(Outh + (size_t)(row + 8) * ldOut + col) = packh2(v10, v11);
      }
    }
  }
}

// ---------------------------------------------------------------------------
// fp32 fallback GEMM (cond embed, K=438), batched over blockIdx.z (batch),
// with pos-emb add fused into the epilogue.
// ---------------------------------------------------------------------------
__global__ __launch_bounds__(256) void gemm_f32(
    const float* __restrict__ In, int ldIn, const float* __restrict__ W,
    const float* __restrict__ bias, const float* __restrict__ pos,
    float* __restrict__ Out, int ldOut, int K) {
  __shared__ float As[16][132];
  __shared__ float Bs[16][68];
  const int tid = threadIdx.x;
  const int tx = tid & 15, ty = tid >> 4;
  const int m0 = blockIdx.y * 128, n0 = blockIdx.x * 64;
  const int bz = blockIdx.z;
  const float* Inb = In + (size_t)bz * tt * ldIn;
  float* Outb = Out + (size_t)bz * Tt * ldOut;
  const int lr = tid >> 2, lc = (tid & 3) * 4;
  float acc[8][4];
#pragma unroll
  for (int r = 0; r < 8; r++)
#pragma unroll
    for (int c = 0; c < 4; c++) acc[r][c] = 0.f;
  for (int kt = 0; kt < K; kt += 16) {
#pragma unroll
    for (int qq = 0; qq < 4; qq++) {
      int k = kt + lc + qq;
      float av0 = 0.f, av1 = 0.f, bv = 0.f;
      if (k < K) {
        av0 = Inb[(size_t)(m0 + lr) * ldIn + k];
        av1 = Inb[(size_t)(m0 + lr + 64) * ldIn + k];
        bv = W[(size_t)(n0 + lr) * K + k];
      }
      As[lc + qq][lr] = av0;
      As[lc + qq][lr + 64] = av1;
      Bs[lc + qq][lr] = bv;
    }
    __syncthreads();
#pragma unroll
    for (int kk = 0; kk < 16; kk++) {
      float4 t0 = *(const float4*)&As[kk][ty * 8];
      float4 t1 = *(const float4*)&As[kk][ty * 8 + 4];
      float4 t2 = *(const float4*)&Bs[kk][tx * 4];
      float a[8] = {t0.x, t0.y, t0.z, t0.w, t1.x, t1.y, t1.z, t1.w};
      float bb[4] = {t2.x, t2.y, t2.z, t2.w};
#pragma unroll
      for (int r = 0; r < 8; r++)
#pragma unroll
        for (int c = 0; c < 4; c++) acc[r][c] += a[r] * bb[c];
    }
    __syncthreads();
  }
  float bv[4];
#pragma unroll
  for (int c = 0; c < 4; c++) bv[c] = bias ? bias[n0 + tx * 4 + c] : 0.f;
#pragma unroll
  for (int r = 0; r < 8; r++) {
    int row = m0 + ty * 8 + r;
    const float* pr = pos + (size_t)row * Cc + n0 + tx * 4;
    float* op = Outb + (size_t)row * ldOut + n0 + tx * 4;
    float4 o = {acc[r][0] + bv[0] + pr[0], acc[r][1] + bv[1] + pr[1],
                acc[r][2] + bv[2] + pr[2], acc[r][3] + bv[3] + pr[3]};
    *(float4*)op = o;
  }
}

// ---------------------------------------------------------------------------
// LayerNorm (proven): block-per-row, fp32 in, fp16 out
// ---------------------------------------------------------------------------
__global__ __launch_bounds__(256) void ln_kernel(
    const float* __restrict__ x, const float* __restrict__ w,
    const float* __restrict__ b, __half* __restrict__ out) {
  const int row = blockIdx.x;
  const int tid = threadIdx.x;
  const float* xr = x + (size_t)row * Cc;
  float v0 = xr[tid], v1 = xr[tid + 256], v2 = xr[tid + 512];
  __shared__ float red[8];
  float s = v0 + v1 + v2;
#pragma unroll
  for (int o = 16; o > 0; o >>= 1) s += __shfl_xor_sync(0xffffffffu, s, o);
  if ((tid & 31) == 0) red[tid >> 5] = s;
  __syncthreads();
  float mean = (red[0] + red[1] + red[2] + red[3] + red[4] + red[5] + red[6] + red[7]) * (1.f / 768.f);
  float d0 = v0 - mean, d1 = v1 - mean, d2 = v2 - mean;
  float sq = d0 * d0 + d1 * d1 + d2 * d2;
  __syncthreads();
#pragma unroll
  for (int o = 16; o > 0; o >>= 1) sq += __shfl_xor_sync(0xffffffffu, sq, o);
  if ((tid & 31) == 0) red[tid >> 5] = sq;
  __syncthreads();
  float var = (red[0] + red[1] + red[2] + red[3] + red[4] + red[5] + red[6] + red[7]) * (1.f / 768.f);
  float inv = rsqrtf(var + 1e-5f);
  __half* orow = out + (size_t)row * Cc;
  orow[tid] = __float2half_rn(d0 * inv * w[tid] + b[tid]);
  orow[tid + 256] = __float2half_rn(d1 * inv * w[tid + 256] + b[tid + 256]);
  orow[tid + 512] = __float2half_rn(d2 * inv * w[tid + 512] + b[tid + 512]);
}

// ---------------------------------------------------------------------------
// Embed token rows only (rows tt..3tt per batch): x = tok[idx] + pos
// ---------------------------------------------------------------------------
__global__ __launch_bounds__(256) void embed_tok(
    const int* __restrict__ iu, const int* __restrict__ idn,
    const float* __restrict__ tu, const float* __restrict__ td,
    const float* __restrict__ pos, float* __restrict__ x) {
  int gidx = blockIdx.x * 256 + threadIdx.x;
  int c = gidx % Cc;
  int r2 = gidx / Cc;
  int i2 = r2 % (2 * tt);
  int b = r2 / (2 * tt);
  int i = tt + i2;
  float p = pos[i * Cc + c];
  float v;
  if (i2 < tt) v = tu[(size_t)iu[b * tt + i2] * Cc + c] + p;
  else v = td[(size_t)idn[b * tt + (i2 - tt)] * Cc + c] + p;
  x[((size_t)b * Tt + i) * Cc + c] = v;
}

// ---------------------------------------------------------------------------
// fp16 flash attention with register prefetch of next K/V tile.
// Block = (qtile 64, head, batch), 128 threads.
// ---------------------------------------------------------------------------
__global__ __launch_bounds__(128) void attn_h(
    const __half* __restrict__ qkv, __half* __restrict__ y) {
  __shared__ __align__(16) unsigned Qs[64][36];
  __shared__ __align__(16) unsigned Ks[64][36];
  __shared__ __align__(16) unsigned Vt[64][36];
  __shared__ __align__(16) unsigned Ps[64][36];
  __half(*VtH)[72] = (__half(*)[72])Vt;

  const int qt = blockIdx.x, h = blockIdx.y, b = blockIdx.z;
  const int tid = threadIdx.x, lane = tid & 31, warp = tid >> 5;
  const int g = lane >> 2, q = lane & 3;

  const int lrow = tid >> 1;
  const int lwo = (tid & 1) * 16;
  const int ldh = lwo * 2;

  {
    const __half* qr = qkv + (size_t)(b * Tt + qt * 64 + lrow) * 2304 + h * 64 + ldh;
#pragma unroll
    for (int j = 0; j < 4; j++)
      *(uint4*)&Qs[lrow][lwo + j * 4] = *(const uint4*)(qr + j * 8);
  }

  float m0r = -1e30f, m1r = -1e30f, l0 = 0.f, l1 = 0.f;
  float accO[8][4];
#pragma unroll
  for (int nb = 0; nb < 8; nb++)
#pragma unroll
    for (int r = 0; r < 4; r++) accO[nb][r] = 0.f;

  const int a = qt & 3;
  const int r0 = warp * 16 + g, r1 = r0 + 8;

  uint4 kreg[4], vreg[4];
  auto ldtile = [&](int kt) {
    const __half* kr = qkv + (size_t)(b * Tt + kt * 64 + lrow) * 2304 + 768 + h * 64 + ldh;
    const __half* vr = kr + 768;
#pragma unroll
    for (int j = 0; j < 4; j++) kreg[j] = *(const uint4*)(kr + j * 8);
#pragma unroll
    for (int j = 0; j < 4; j++) vreg[j] = *(const uint4*)(vr + j * 8);
  };
  auto next_valid = [&](int kt) {
    for (int k2 = kt + 1; k2 < 12; k2++)
      if ((k2 & 3) <= a) return k2;
    return 12;
  };

  int kt = ((0 & 3) <= a) ? 0 : next_valid(0);  // first valid (always 0)
  ldtile(kt);

  for (; kt < 12; ) {
    const bool diag = ((kt & 3) == a);
    __syncthreads();  // prior PV done reading Ks/Vt (Q store ordered on 1st pass)

    // commit prefetched regs to smem
#pragma unroll
    for (int j = 0; j < 4; j++) *(uint4*)&Ks[lrow][lwo + j * 4] = kreg[j];
#pragma unroll
    for (int j = 0; j < 4; j++) {
      const unsigned w4[4] = {vreg[j].x, vreg[j].y, vreg[j].z, vreg[j].w};
#pragma unroll
      for (int p2 = 0; p2 < 4; p2++) {
        __half2 v = *(const __half2*)&w4[p2];
        int d2 = j * 8 + p2 * 2;
        VtH[ldh + d2][lrow] = __low2half(v);
        VtH[ldh + d2 + 1][lrow] = __high2half(v);
      }
    }

    // prefetch next valid tile while computing this one
    const int ktn = next_valid(kt);
    __syncthreads();
    if (ktn < 12) ldtile(ktn);

    float s[8][4];
#pragma unroll
    for (int nb = 0; nb < 8; nb++)
#pragma unroll
      for (int r = 0; r < 4; r++) s[nb][r] = 0.f;
#pragma unroll
    for (int ks = 0; ks < 4; ks++) {
      const int k0 = ks * 8;
      unsigned aa[4] = {Qs[r0][k0 + q], Qs[r1][k0 + q],
                        Qs[r0][k0 + q + 4], Qs[r1][k0 + q + 4]};
#pragma unroll
      for (int nb = 0; nb < 8; nb++) {
        const int c = nb * 8 + g;
        unsigned bb[2] = {Ks[c][k0 + q], Ks[c][k0 + q + 4]};
        mma16h(s[nb], aa, bb);
      }
    }

    float mx0 = -1e30f, mx1 = -1e30f;
#pragma unroll
    for (int nb = 0; nb < 8; nb++) {
      int c0 = nb * 8 + 2 * q;
      float v00 = s[nb][0] * 0.125f, v01 = s[nb][1] * 0.125f;
      float v10 = s[nb][2] * 0.125f, v11 = s[nb][3] * 0.125f;
      if (diag) {
        if (c0 > r0) v00 = -1e30f;
        if (c0 + 1 > r0) v01 = -1e30f;
        if (c0 > r1) v10 = -1e30f;
        if (c0 + 1 > r1) v11 = -1e30f;
      }
      s[nb][0] = v00; s[nb][1] = v01; s[nb][2] = v10; s[nb][3] = v11;
      mx0 = fmaxf(mx0, fmaxf(v00, v01));
      mx1 = fmaxf(mx1, fmaxf(v10, v11));
    }
    mx0 = fmaxf(mx0, __shfl_xor_sync(0xffffffffu, mx0, 1));
    mx0 = fmaxf(mx0, __shfl_xor_sync(0xffffffffu, mx0, 2));
    mx1 = fmaxf(mx1, __shfl_xor_sync(0xffffffffu, mx1, 1));
    mx1 = fmaxf(mx1, __shfl_xor_sync(0xffffffffu, mx1, 2));

    float mn0 = fmaxf(m0r, mx0), mn1 = fmaxf(m1r, mx1);
    float cf0 = __expf(m0r - mn0), cf1 = __expf(m1r - mn1);
    m0r = mn0; m1r = mn1;

    float rs0 = 0.f, rs1 = 0.f;
#pragma unroll
    for (int nb = 0; nb < 8; nb++) {
      float p00 = __expf(s[nb][0] - mn0);
      float p01 = __expf(s[nb][1] - mn0);
      float p10 = __expf(s[nb][2] - mn1);
      float p11 = __expf(s[nb][3] - mn1);
      rs0 += p00 + p01;
      rs1 += p10 + p11;
      Ps[r0][nb * 4 + q] = packh2(p00, p01);
      Ps[r1][nb * 4 + q] = packh2(p10, p11);
    }
    rs0 += __shfl_xor_sync(0xffffffffu, rs0, 1);
    rs0 += __shfl_xor_sync(0xffffffffu, rs0, 2);
    rs1 += __shfl_xor_sync(0xffffffffu, rs1, 1);
    rs1 += __shfl_xor_sync(0xffffffffu, rs1, 2);
    l0 = l0 * cf0 + rs0;
    l1 = l1 * cf1 + rs1;
#pragma unroll
    for (int nb = 0; nb < 8; nb++) {
      accO[nb][0] *= cf0; accO[nb][1] *= cf0;
      accO[nb][2] *= cf1; accO[nb][3] *= cf1;
    }
    __syncthreads();

#pragma unroll
    for (int ks = 0; ks < 4; ks++) {
      const int k0 = ks * 8;
      unsigned aa[4] = {Ps[r0][k0 + q], Ps[r1][k0 + q],
                        Ps[r0][k0 + q + 4], Ps[r1][k0 + q + 4]};
#pragma unroll
      for (int nb = 0; nb < 8; nb++) {
        const int c = nb * 8 + g;
        unsigned bb[2] = {Vt[c][k0 + q], Vt[c][k0 + q + 4]};
        mma16h(accO[nb], aa, bb);
      }
    }
    kt = ktn;
  }

  float inv0 = 1.f / l0, inv1 = 1.f / l1;
#pragma unroll
  for (int nb = 0; nb < 8; nb++) {
    int c0 = nb * 8 + 2 * q;
    __half* y0 = y + (size_t)(b * Tt + qt * 64 + r0) * Cc + h * 64 + c0;
    *(unsigned*)y0 = packh2(accO[nb][0] * inv0, accO[nb][1] * inv0);
    *(unsigned*)(y0 + 8 * Cc) = packh2(accO[nb][2] * inv1, accO[nb][3] * inv1);
  }
}

// ---------------------------------------------------------------------------
// Launcher
// ---------------------------------------------------------------------------
extern "C" void kernel_launch(void* const* d_in, const int* in_sizes, int n_in,
                              void* d_out, int out_size) {
  const int* idx_up = nullptr; const int* idx_down = nullptr;
  const float *cond = 0, *tok_up = 0, *tok_down = 0, *pos = 0, *cond_w = 0, *cond_b = 0;
  const float *lnf_w = 0, *lnf_b = 0, *hup = 0, *hdn = 0;
  const float *ln1[2] = {0, 0}, *ln2[2] = {0, 0}, *qkvw[2] = {0, 0}, *qkvb[2] = {0, 0};
  const float *projw[2] = {0, 0}, *projb[2] = {0, 0};
  const float *fc1w[2] = {0, 0}, *fc1b[2] = {0, 0}, *fc2w[2] = {0, 0}, *fc2b[2] = {0, 0};

  int c512 = 0, c393 = 0, c768 = 0, c9216 = 0, cqw = 0, cqb = 0, cpw = 0, c4608 = 0,
      cfw = 0, cfb = 0;
  for (int i = 0; i < n_in; i++) {
    const float* f = (const float*)d_in[i];
    switch (in_sizes[i]) {
      case 512:       if (c512 == 0) idx_up = (const int*)f; else idx_down = (const int*)f; c512++; break;
      case 224256:    cond = f; break;
      case 393216:    if (c393 == 0) tok_up = f; else if (c393 == 1) tok_down = f;
                      else if (c393 == 2) hup = f; else hdn = f; c393++; break;
      case 589824:    pos = f; break;
      case 336384:    cond_w = f; break;
      case 768:       if (c768 == 0) cond_b = f; else if (c768 == 1) lnf_w = f; else lnf_b = f; c768++; break;
      case 9216:      if (c9216 == 0) ln1[0] = f; else if (c9216 == 1) ln2[0] = f;
                      else if (c9216 == 2) ln1[1] = f; else ln2[1] = f; c9216++; break;
      case 10616832:  qkvw[cqw++] = f; break;
      case 13824:     qkvb[cqb++] = f; break;
      case 3538944:   projw[cpw++] = f; break;
      case 4608:      if (c4608 == 0) projb[0] = f; else if (c4608 == 1) fc2b[0] = f;
                      else if (c4608 == 2) projb[1] = f; else fc2b[1] = f; c4608++; break;
      case 14155776:  if (cfw == 0) fc1w[0] = f; else if (cfw == 1) fc2w[0] = f;
                      else if (cfw == 2) fc1w[1] = f; else fc2w[1] = f; cfw++; break;
      case 18432:     fc1b[cfb++] = f; break;
      default: break;
    }
  }

  float* x;
  __half *hh, *yh, *bigh, *wh;
  cudaGetSymbolAddress((void**)&x, g_x);
  cudaGetSymbolAddress((void**)&hh, g_hh);
  cudaGetSymbolAddress((void**)&yh, g_yh);
  cudaGetSymbolAddress((void**)&bigh, g_bigh);
  cudaGetSymbolAddress((void**)&wh, g_wh);

  const size_t off_qkv[2] = {OFF_QKV0, OFF_QKV1};
  const size_t off_proj[2] = {OFF_PROJ0, OFF_PROJ1};
  const size_t off_fc1[2] = {OFF_FC10, OFF_FC11};
  const size_t off_fc2[2] = {OFF_FC20, OFF_FC21};

  // --- Weight conversion: one fused launch ---
  cvt_all<<<83712, 256>>>(qkvw[0], qkvw[1], projw[0], projw[1],
                          fc1w[0], fc1w[1], fc2w[0], fc2w[1], hup, hdn, wh);

  const int SM128 = 4 * (128 * 80) + 4 * (128 * 80);  // 81920
  const int SM64 = 4 * (64 * 80) + 4 * (128 * 80);    // 61440
  cudaFuncSetAttribute(gemm_h<128, 3>, cudaFuncAttributeMaxDynamicSharedMemorySize, SM128);
  cudaFuncSetAttribute(gemm_h<128, 1>, cudaFuncAttributeMaxDynamicSharedMemorySize, SM128);
  cudaFuncSetAttribute(gemm_h<64, 2>, cudaFuncAttributeMaxDynamicSharedMemorySize, SM64);
  cudaFuncSetAttribute(gemm_h<64, 0>, cudaFuncAttributeMaxDynamicSharedMemorySize, SM64);

  // --- Embed: one batched cond GEMM (pos fused) + token rows ---
  gemm_f32<<<dim3(Cc / 64, tt / 128, Bz), 256>>>(
      cond, 438, cond_w, cond_b, pos, x, Cc, 438);
  embed_tok<<<(Bz * 2 * tt * Cc) / 256, 256>>>(idx_up, idx_down, tok_up, tok_down, pos, x);

  // --- 2 stacks x 6 blocks ---
  for (int st = 0; st < 2; st++) {
    for (int l = 0; l < 6; l++) {
      const float* w1 = ln1[st] + (size_t)l * 2 * Cc;
      ln_kernel<<<Bz * Tt, 256>>>(x, w1, w1 + Cc, hh);
      gemm_h<128, 3><<<dim3(3 * Cc / 128, Bz * Tt / 128), 256, SM128>>>(
          hh, Cc, wh + off_qkv[st] + (size_t)l * 3 * Cc * Cc,
          qkvb[st] + (size_t)l * 3 * Cc, bigh, 3 * Cc, Cc, 0, 0);
      attn_h<<<dim3(Tt / 64, Hh, Bz), 128>>>(bigh, yh);
      gemm_h<64, 2><<<dim3(Cc / 128, Bz * Tt / 64), 256, SM64>>>(
          yh, Cc, wh + off_proj[st] + (size_t)l * Cc * Cc,
          projb[st] + (size_t)l * Cc, x, Cc, Cc, 0, 0);
      const float* w2 = ln2[st] + (size_t)l * 2 * Cc;
      ln_kernel<<<Bz * Tt, 256>>>(x, w2, w2 + Cc, hh);
      gemm_h<128, 1><<<dim3(FC / 128, Bz * Tt / 128), 256, SM128>>>(
          hh, Cc, wh + off_fc1[st] + (size_t)l * FC * Cc,
          fc1b[st] + (size_t)l * FC, bigh, FC, Cc, 0, 0);
      gemm_h<64, 2><<<dim3(Cc / 128, Bz * Tt / 64), 256, SM64>>>(
          bigh, FC, wh + off_fc2[st] + (size_t)l * Cc * FC,
          fc2b[st] + (size_t)l * Cc, x, Cc, FC, 0, 0);
    }
  }

  // --- Final LN + heads (batched over batch via grid.z) ---
  ln_kernel<<<Bz * Tt, 256>>>(x, lnf_w, lnf_b, hh);
  float* out = (float*)d_out;
  gemm_h<64, 0><<<dim3(Vv / 128, tt / 64, Bz), 256, SM64>>>(
      hh + (size_t)tt * Cc, Cc, wh + OFF_HUP, nullptr,
      out, Vv, Cc, Tt * Cc, tt * Vv);
  gemm_h<64, 0><<<dim3(Vv / 128, tt / 64, Bz), 256, SM64>>>(
      hh + (size_t)(2 * tt) * Cc, Cc, wh + OFF_HDN, nullptr,
      out + (size_t)Bz * tt * Vv, Vv, Cc, Tt * Cc, tt * Vv);
  (void)out_size; (void)n_in;
}